// round 16
// baseline (speedup 1.0000x reference)
#include <cuda_runtime.h>
#include <cuda_fp16.h>
#include <cstdint>

#define N_MAX   50000
#define E_MAX   800000
#define G_CNT   512
#define FDIM    128
#define OUTD    200
#define SCAN_B  1024
#define AP      136                    // smem pitch in halves (conflict-free ldmatrix)
#define GEMM_SMEM (2 * 128 * AP * 2)   // A tile + W tile, bytes (69632)
#define WCONV_BLOCKS 64                // 64*256 = 16384 = FDIM*FDIM
#define FILL_BLOCKS  784               // 784*256 = 200704 >= 2n and >= E/4

// PDL rules (learned R15): triggers cascade from kernel START, so pre-wait code
// may ONLY read harness inputs / thread-local state. ALL reads of data produced
// by ANY earlier kernel must come after PDL_WAIT (transitively safe: predecessor
// completion implies its wait passed, inductively to the chain head).
#define PDL_TRIGGER() asm volatile("griddepcontrol.launch_dependents;")
#define PDL_WAIT()    asm volatile("griddepcontrol.wait;" ::: "memory")

// ---------------- device scratch (static, no allocation) ----------------
__device__ __align__(128) __half g_xh[N_MAX * FDIM];    // half features; also final-layer output for pooling
__device__ __align__(128) __half g_aggh[N_MAX * FDIM];  // half aggregated (GEMM input)
__device__ __align__(128) __half g_Wh[3 * FDIM * FDIM]; // fp16 layer weights
__device__ int   g_deg[2 * N_MAX];
__device__ float g_norm_out[N_MAX];
__device__ float g_norm_in[N_MAX];
__device__ int   g_row_off[N_MAX + 1];
__device__ int   g_cursor[N_MAX];      // initialized to exclusive row offset by k_scan
__device__ int   g_esrc[E_MAX];
__device__ int   g_bsum[64];
__device__ unsigned g_count = 0;            // grid-barrier arrivals
__device__ volatile unsigned g_gen = 0;     // grid-barrier generation (monotonic across replays)

// ---------------- k_prep: fp16 weight conversion + degree histogram ----------------
// First kernel: reads only harness inputs, no wait needed.
__global__ void k_prep(const float* __restrict__ W0, const float* __restrict__ W1,
                       const float* __restrict__ W2,
                       const int* __restrict__ src, const int* __restrict__ dst,
                       int E, int n) {
    PDL_TRIGGER();
    if (blockIdx.x < WCONV_BLOCKS) {
        int i = blockIdx.x * 256 + threadIdx.x;   // exactly FDIM*FDIM threads
        g_Wh[i]                   = __float2half_rn(__ldg(&W0[i]));
        g_Wh[FDIM * FDIM + i]     = __float2half_rn(__ldg(&W1[i]));
        g_Wh[2 * FDIM * FDIM + i] = __float2half_rn(__ldg(&W2[i]));
    } else {
        const int4* s4 = (const int4*)src;
        const int4* d4 = (const int4*)dst;
        int e4 = E >> 2;
        int nb = gridDim.x - WCONV_BLOCKS;
        int t = (blockIdx.x - WCONV_BLOCKS) * 256 + threadIdx.x;
        for (int i = t; i < e4; i += nb * 256) {
            int4 a = __ldg(&s4[i]);
            int4 b = __ldg(&d4[i]);
            atomicAdd(&g_deg[a.x], 1); atomicAdd(&g_deg[a.y], 1);
            atomicAdd(&g_deg[a.z], 1); atomicAdd(&g_deg[a.w], 1);
            atomicAdd(&g_deg[n + b.x], 1); atomicAdd(&g_deg[n + b.y], 1);
            atomicAdd(&g_deg[n + b.z], 1); atomicAdd(&g_deg[n + b.w], 1);
        }
        int base = e4 << 2;
        if (t < E - base) {
            atomicAdd(&g_deg[src[base + t]], 1);
            atomicAdd(&g_deg[n + dst[base + t]], 1);
        }
    }
}

// ---------------- k_scan: fused two-phase scan with software grid barrier ----------------
__global__ void __launch_bounds__(SCAN_B) k_scan(int n, int nb) {
    __shared__ int wsum[32];
    const int tid = threadIdx.x, lane = tid & 31, wid = tid >> 5;
    const int i = blockIdx.x * SCAN_B + tid;

    PDL_TRIGGER();
    PDL_WAIT();          // g_deg produced by k_prep

    int v = 0;
    if (i < n) {
        v = g_deg[n + i];
        g_norm_out[i] = rsqrtf(fmaxf((float)g_deg[i], 1.0f));
        g_norm_in[i]  = rsqrtf(fmaxf((float)v, 1.0f));
    }
    int x = v;
    #pragma unroll
    for (int off = 1; off < 32; off <<= 1) {
        int t = __shfl_up_sync(0xffffffffu, x, off);
        if (lane >= off) x += t;
    }
    if (lane == 31) wsum[wid] = x;
    __syncthreads();
    if (wid == 0) {
        int w = wsum[lane];
        #pragma unroll
        for (int off = 1; off < 32; off <<= 1) {
            int t = __shfl_up_sync(0xffffffffu, w, off);
            if (lane >= off) w += t;
        }
        wsum[lane] = w;
    }
    __syncthreads();
    int incl = x + (wid > 0 ? wsum[wid - 1] : 0);
    if (i < n) g_row_off[i + 1] = incl;
    if (tid == SCAN_B - 1) g_bsum[blockIdx.x] = incl;
    if (i == 0) g_row_off[0] = 0;

    // grid barrier (generation counter; deterministic across replays)
    __syncthreads();
    __threadfence();
    if (tid == 0) {
        unsigned gen = g_gen;
        if (atomicAdd(&g_count, 1u) == gridDim.x - 1) {
            g_count = 0;
            __threadfence();
            g_gen = gen + 1;
        } else {
            while (g_gen == gen) { }
        }
    }
    __syncthreads();
    __threadfence();

    __shared__ int soff;
    if (tid < 32) {
        int l = tid;
        int bid = blockIdx.x;
        int s = (l < nb && l < bid) ? g_bsum[l] : 0;
        if (l + 32 < nb && l + 32 < bid) s += g_bsum[l + 32];
        #pragma unroll
        for (int off = 16; off > 0; off >>= 1)
            s += __shfl_down_sync(0xffffffffu, s, off);
        if (l == 0) soff = s;
    }
    __syncthreads();
    if (i < n) {
        int total = incl + soff;
        g_row_off[i + 1] = total;
        g_cursor[i] = total - v;     // exclusive offset = fill cursor start
    }
}

// ---------------- k_build: CSR fill (single-atomic) + node features, overlapped ----------------
__global__ void k_build(const int* __restrict__ src, const int* __restrict__ dst,
                        int E, int n2,
                        const int* __restrict__ nid, const int* __restrict__ z,
                        const float* __restrict__ init_embed,
                        const float* __restrict__ z_table, int n) {
    PDL_TRIGGER();
    PDL_WAIT();          // g_cursor / g_norm_out produced by k_scan
    if (blockIdx.x < FILL_BLOCKS) {
        int t = blockIdx.x * 256 + threadIdx.x;
        if (t < n2) g_deg[t] = 0;                 // deg is dead; re-zero for next call
        const int4* s4 = (const int4*)src;
        const int4* d4 = (const int4*)dst;
        int e4 = E >> 2;
        for (int i = t; i < e4; i += FILL_BLOCKS * 256) {
            int4 a = __ldg(&s4[i]);
            int4 b = __ldg(&d4[i]);
            g_esrc[atomicAdd(&g_cursor[b.x], 1)] = a.x;
            g_esrc[atomicAdd(&g_cursor[b.y], 1)] = a.y;
            g_esrc[atomicAdd(&g_cursor[b.z], 1)] = a.z;
            g_esrc[atomicAdd(&g_cursor[b.w], 1)] = a.w;
        }
        int base = e4 << 2;
        if (t < E - base) {
            int d = dst[base + t];
            g_esrc[atomicAdd(&g_cursor[d], 1)] = src[base + t];
        }
    } else {
        int total = n * 32;
        int nb = gridDim.x - FILL_BLOCKS;
        for (int idx = (blockIdx.x - FILL_BLOCKS) * 256 + threadIdx.x; idx < total;
             idx += nb * 256) {
            int node = idx >> 5, q = idx & 31;
            float4 v;
            if (q < 16) v = __ldg(&((const float4*)init_embed)[(long)nid[node] * 16 + q]);
            else        v = __ldg(&((const float4*)z_table)[(long)z[node] * 16 + (q - 16)]);
            float s = g_norm_out[node];
            __half2 h0 = __floats2half2_rn(v.x * s, v.y * s);
            __half2 h1 = __floats2half2_rn(v.z * s, v.w * s);
            uint2 pk;
            pk.x = *(unsigned*)&h0;
            pk.y = *(unsigned*)&h1;
            ((uint2*)g_xh)[node * 32 + q] = pk;
        }
    }
}

// ---------------- SpMM gather-reduce: half-warp per dst row (R12 validated form) ----------------
// ALL device-global reads after PDL_WAIT.
__global__ void __launch_bounds__(256) k_spmm(int n) {
    PDL_TRIGGER();
    PDL_WAIT();          // g_xh / g_esrc / g_row_off / g_norm_in all safe after wait
    int row = blockIdx.x * 16 + (threadIdx.x >> 4);
    int hl  = threadIdx.x & 15;
    if (row >= n) return;
    int e0 = g_row_off[row], e1 = g_row_off[row + 1];
    const uint4* xh = (const uint4*)g_xh;   // 16 uint4 per row
    float a0 = 0.f, a1 = 0.f, a2 = 0.f, a3 = 0.f, a4 = 0.f, a5 = 0.f, a6 = 0.f, a7 = 0.f;
    int e = e0;
    for (; e + 3 < e1; e += 4) {
        int s0 = __ldg(&g_esrc[e]);
        int s1 = __ldg(&g_esrc[e + 1]);
        int s2 = __ldg(&g_esrc[e + 2]);
        int s3 = __ldg(&g_esrc[e + 3]);
        uint4 p0 = __ldg(&xh[s0 * 16 + hl]);
        uint4 p1 = __ldg(&xh[s1 * 16 + hl]);
        uint4 p2 = __ldg(&xh[s2 * 16 + hl]);
        uint4 p3 = __ldg(&xh[s3 * 16 + hl]);
        __half2 t0 = __hadd2(__hadd2(*(__half2*)&p0.x, *(__half2*)&p1.x),
                             __hadd2(*(__half2*)&p2.x, *(__half2*)&p3.x));
        __half2 t1 = __hadd2(__hadd2(*(__half2*)&p0.y, *(__half2*)&p1.y),
                             __hadd2(*(__half2*)&p2.y, *(__half2*)&p3.y));
        __half2 t2 = __hadd2(__hadd2(*(__half2*)&p0.z, *(__half2*)&p1.z),
                             __hadd2(*(__half2*)&p2.z, *(__half2*)&p3.z));
        __half2 t3 = __hadd2(__hadd2(*(__half2*)&p0.w, *(__half2*)&p1.w),
                             __hadd2(*(__half2*)&p2.w, *(__half2*)&p3.w));
        float2 f;
        f = __half22float2(t0); a0 += f.x; a1 += f.y;
        f = __half22float2(t1); a2 += f.x; a3 += f.y;
        f = __half22float2(t2); a4 += f.x; a5 += f.y;
        f = __half22float2(t3); a6 += f.x; a7 += f.y;
    }
    for (; e < e1; e++) {
        int s0 = __ldg(&g_esrc[e]);
        uint4 p0 = __ldg(&xh[s0 * 16 + hl]);
        float2 f;
        f = __half22float2(*(__half2*)&p0.x); a0 += f.x; a1 += f.y;
        f = __half22float2(*(__half2*)&p0.y); a2 += f.x; a3 += f.y;
        f = __half22float2(*(__half2*)&p0.z); a4 += f.x; a5 += f.y;
        f = __half22float2(*(__half2*)&p0.w); a6 += f.x; a7 += f.y;
    }
    float ni = g_norm_in[row];
    __half2 h0 = __floats2half2_rn(a0 * ni, a1 * ni);
    __half2 h1 = __floats2half2_rn(a2 * ni, a3 * ni);
    __half2 h2 = __floats2half2_rn(a4 * ni, a5 * ni);
    __half2 h3 = __floats2half2_rn(a6 * ni, a7 * ni);
    uint4 pk;
    pk.x = *(unsigned*)&h0;
    pk.y = *(unsigned*)&h1;
    pk.z = *(unsigned*)&h2;
    pk.w = *(unsigned*)&h3;
    ((uint4*)g_aggh)[row * 16 + hl] = pk;
}

// ---------------- HMMA GEMM: out = act(g_aggh @ g_Wh[layer] + b) ----------------
// W staging moved AFTER the wait (g_Wh is kernel-produced data).
__global__ void __launch_bounds__(256, 3) k_gemm_h(int layer,
                                                   const float* __restrict__ bias,
                                                   int n, int mode) {
    extern __shared__ __half sh[];
    __half* As = sh;               // [128][AP]
    __half* Ws = sh + 128 * AP;    // [128][AP]
    const int tid = threadIdx.x;
    const int w = tid >> 5, lane = tid & 31;
    const int row0 = blockIdx.x * 128;

    PDL_TRIGGER();
    PDL_WAIT();          // g_aggh (k_spmm) and transitively g_Wh (k_prep)

    {
        const uint4* asrc = (const uint4*)g_aggh;
        const uint4* wsrc = (const uint4*)(g_Wh + layer * FDIM * FDIM);
        int r = tid >> 1;
        int s0 = (tid & 1) * 8;
        int grow = row0 + r;
        #pragma unroll
        for (int s = 0; s < 8; s++) {
            uint4 av = make_uint4(0u, 0u, 0u, 0u);
            if (grow < n) av = __ldg(&asrc[grow * 16 + s0 + s]);
            *(uint4*)&As[r * AP + (s0 + s) * 8] = av;
            uint4 wv = __ldg(&wsrc[r * 16 + s0 + s]);
            *(uint4*)&Ws[r * AP + (s0 + s) * 8] = wv;
        }
    }
    __syncthreads();

    float acc[16][4];
    #pragma unroll
    for (int nt = 0; nt < 16; nt++)
        #pragma unroll
        for (int q = 0; q < 4; q++) acc[nt][q] = 0.f;

    #pragma unroll
    for (int kk = 0; kk < 8; kk++) {
        unsigned a0, a1, a2, a3;
        {
            int arow = 16 * w + (lane & 15);
            int acol = kk * 16 + ((lane >> 4) << 3);
            unsigned aaddr = (unsigned)__cvta_generic_to_shared(&As[arow * AP + acol]);
            asm volatile("ldmatrix.sync.aligned.m8n8.x4.shared.b16 {%0,%1,%2,%3}, [%4];"
                         : "=r"(a0), "=r"(a1), "=r"(a2), "=r"(a3) : "r"(aaddr));
        }
        int brow = kk * 16 + (lane & 15);
        unsigned bbase = (unsigned)__cvta_generic_to_shared(&Ws[brow * AP]);
        #pragma unroll
        for (int nt = 0; nt < 16; nt++) {
            unsigned b0, b1;
            asm volatile("ldmatrix.sync.aligned.m8n8.x2.trans.shared.b16 {%0,%1}, [%2];"
                         : "=r"(b0), "=r"(b1) : "r"(bbase + nt * 16u));
            asm volatile("mma.sync.aligned.m16n8k16.row.col.f32.f16.f16.f32 "
                         "{%0,%1,%2,%3}, {%4,%5,%6,%7}, {%8,%9}, {%0,%1,%2,%3};"
                         : "+f"(acc[nt][0]), "+f"(acc[nt][1]), "+f"(acc[nt][2]), "+f"(acc[nt][3])
                         : "r"(a0), "r"(a1), "r"(a2), "r"(a3), "r"(b0), "r"(b1));
        }
    }

    const int rlo = row0 + 16 * w + (lane >> 2);
    const int rhi = rlo + 8;
    const int cbase = (lane & 3) * 2;
    float slo = 1.f, shi = 1.f;
    if (mode) {
        if (rlo < n) slo = g_norm_out[rlo];
        if (rhi < n) shi = g_norm_out[rhi];
    }
    #pragma unroll
    for (int nt = 0; nt < 16; nt++) {
        int c = nt * 8 + cbase;
        float b0v = __ldg(&bias[c]), b1v = __ldg(&bias[c + 1]);
        if (rlo < n) {
            float v0 = acc[nt][0] + b0v, v1 = acc[nt][1] + b1v;
            if (mode) { v0 = fmaxf(v0, 0.f) * slo; v1 = fmaxf(v1, 0.f) * slo; }
            __half2 h = __floats2half2_rn(v0, v1);
            *(__half2*)&g_xh[rlo * FDIM + c] = h;
        }
        if (rhi < n) {
            float v2 = acc[nt][2] + b0v, v3 = acc[nt][3] + b1v;
            if (mode) { v2 = fmaxf(v2, 0.f) * shi; v3 = fmaxf(v3, 0.f) * shi; }
            __half2 h = __floats2half2_rn(v2, v3);
            *(__half2*)&g_xh[rhi * FDIM + c] = h;
        }
    }
}

// ---------------- fused pooling + MLP head ----------------
// Binary searches read only gid (harness input) -> legitimately pre-wait.
__global__ void __launch_bounds__(256) k_pool_mlp(const int* __restrict__ gid, int n,
                                                  const float* __restrict__ lin1_W,
                                                  const float* __restrict__ lin1_b,
                                                  const float* __restrict__ lin2_W,
                                                  const float* __restrict__ lin2_b,
                                                  float* __restrict__ out) {
    __shared__ float gp[4][FDIM];   // per-group partial sums
    __shared__ float gs[FDIM];
    __shared__ float hs[FDIM];
    __shared__ int s_lo, s_hi;
    const int g = blockIdx.x;
    const int tid = threadIdx.x;
    const int grp = tid >> 6;       // node group 0..3
    const int col = tid & 63;       // half2 column 0..63

    if (tid == 0) {
        int lo = 0, hi = n;
        while (lo < hi) { int m = (lo + hi) >> 1; if (__ldg(&gid[m]) < g) lo = m + 1; else hi = m; }
        s_lo = lo;
    } else if (tid == 32) {
        int lo = 0, hi = n;
        while (lo < hi) { int m = (lo + hi) >> 1; if (__ldg(&gid[m]) <= g) lo = m + 1; else hi = m; }
        s_hi = lo;
    }
    __syncthreads();

    PDL_WAIT();          // g_xh produced by final k_gemm_h

    const int lo = s_lo, hi = s_hi;
    {
        float acc0 = 0.f, acc1 = 0.f;
        const __half2* xh2 = (const __half2*)g_xh;
        for (int node = lo + grp; node < hi; node += 4) {
            float2 f = __half22float2(xh2[node * 64 + col]);
            acc0 += f.x; acc1 += f.y;
        }
        gp[grp][2 * col]     = acc0;
        gp[grp][2 * col + 1] = acc1;
    }
    __syncthreads();
    if (tid < FDIM)
        gs[tid] = gp[0][tid] + gp[1][tid] + gp[2][tid] + gp[3][tid];
    __syncthreads();
    if (tid < FDIM) {
        float acc = __ldg(&lin1_b[tid]);
        #pragma unroll 8
        for (int k = 0; k < FDIM; k++)
            acc += gs[k] * __ldg(&lin1_W[k * FDIM + tid]);
        hs[tid] = fmaxf(acc, 0.f);
    }
    __syncthreads();
    for (int c = tid; c < OUTD; c += blockDim.x) {
        float acc = __ldg(&lin2_b[c]);
        #pragma unroll 8
        for (int k = 0; k < FDIM; k++)
            acc += hs[k] * __ldg(&lin2_W[k * OUTD + c]);
        out[g * OUTD + c] = acc;
    }
}

// ---------------- launch helpers ----------------
static void launch_pdl(const void* fn, dim3 grid, dim3 block, size_t smem, void** args) {
    cudaLaunchConfig_t cfg = {};
    cfg.gridDim = grid;
    cfg.blockDim = block;
    cfg.dynamicSmemBytes = smem;
    cfg.stream = 0;
    cudaLaunchAttribute at[1];
    at[0].id = cudaLaunchAttributeProgrammaticStreamSerialization;
    at[0].val.programmaticStreamSerializationAllowed = 1;
    cfg.attrs = at;
    cfg.numAttrs = 1;
    cudaLaunchKernelExC(&cfg, fn, args);
}

extern "C" void kernel_launch(void* const* d_in, const int* in_sizes, int n_in,
                              void* d_out, int out_size) {
    const int*   nid        = (const int*)  d_in[0];
    const int*   z          = (const int*)  d_in[1];
    const int*   src        = (const int*)  d_in[2];
    const int*   dst        = (const int*)  d_in[3];
    const int*   graph_id   = (const int*)  d_in[4];
    const float* init_embed = (const float*)d_in[5];
    const float* z_table    = (const float*)d_in[6];
    const float* W0 = (const float*)d_in[7];
    const float* b0 = (const float*)d_in[8];
    const float* W1 = (const float*)d_in[9];
    const float* b1 = (const float*)d_in[10];
    const float* W2 = (const float*)d_in[11];
    const float* b2 = (const float*)d_in[12];
    const float* lin1_W = (const float*)d_in[13];
    const float* lin1_b = (const float*)d_in[14];
    const float* lin2_W = (const float*)d_in[15];
    const float* lin2_b = (const float*)d_in[16];
    float* out = (float*)d_out;

    int n = in_sizes[0];       // 50000
    int E = in_sizes[2];       // 800000
    int nb = (n + SCAN_B - 1) / SCAN_B;   // 49
    int n2 = 2 * n;

    cudaFuncSetAttribute(k_gemm_h, cudaFuncAttributeMaxDynamicSharedMemorySize, GEMM_SMEM);

    // 1) weights fp16 + degree histogram (normal launch — no predecessor)
    int deg_blocks = ((E >> 2) + 255) / 256;
    k_prep<<<WCONV_BLOCKS + deg_blocks, 256>>>(W0, W1, W2, src, dst, E, n);

    // 2) fused scan (PDL on k_prep)
    {
        void* args[] = { &n, &nb };
        launch_pdl((const void*)k_scan, dim3(nb), dim3(SCAN_B), 0, args);
    }

    // 3) CSR fill + node features (PDL on k_scan)
    {
        int feat_blocks = (n * 32 + 255) / 256;
        void* args[] = { (void*)&src, (void*)&dst, &E, &n2,
                         (void*)&nid, (void*)&z, (void*)&init_embed, (void*)&z_table, &n };
        launch_pdl((const void*)k_build, dim3(FILL_BLOCKS + feat_blocks), dim3(256), 0, args);
    }

    // 4) 3 GCN layers, all PDL-chained
    int spmm_blocks = (n + 15) / 16;
    int gemm_blocks = (n + 127) / 128;
    int layer0 = 0, layer1 = 1, layer2 = 2;
    int relu1 = 1, relu0 = 0;
    {
        void* args[] = { &n };
        launch_pdl((const void*)k_spmm, dim3(spmm_blocks), dim3(256), 0, args);
    }
    {
        void* args[] = { &layer0, (void*)&b0, &n, &relu1 };
        launch_pdl((const void*)k_gemm_h, dim3(gemm_blocks), dim3(256), GEMM_SMEM, args);
    }
    {
        void* args[] = { &n };
        launch_pdl((const void*)k_spmm, dim3(spmm_blocks), dim3(256), 0, args);
    }
    {
        void* args[] = { &layer1, (void*)&b1, &n, &relu1 };
        launch_pdl((const void*)k_gemm_h, dim3(gemm_blocks), dim3(256), GEMM_SMEM, args);
    }
    {
        void* args[] = { &n };
        launch_pdl((const void*)k_spmm, dim3(spmm_blocks), dim3(256), 0, args);
    }
    {
        void* args[] = { &layer2, (void*)&b2, &n, &relu0 };
        launch_pdl((const void*)k_gemm_h, dim3(gemm_blocks), dim3(256), GEMM_SMEM, args);
    }

    // 5) fused pooling + MLP head (PDL on final gemm)
    {
        void* args[] = { (void*)&graph_id, &n, (void*)&lin1_W, (void*)&lin1_b,
                         (void*)&lin2_W, (void*)&lin2_b, (void*)&out };
        launch_pdl((const void*)k_pool_mlp, dim3(G_CNT), dim3(256), 0, args);
    }
}

// round 17
// speedup vs baseline: 1.1555x; 1.1555x over previous
#include <cuda_runtime.h>
#include <cuda_fp16.h>
#include <cstdint>

#define N_MAX   50000
#define E_MAX   800000
#define G_CNT   512
#define FDIM    128
#define OUTD    200
#define SCAN_B  1024
#define AP      136                    // smem pitch in halves (conflict-free ldmatrix)
#define GEMM_SMEM (2 * 128 * AP * 2)   // A tile + W tile, bytes (69632)
#define WCONV_BLOCKS 64                // 64*256 = 16384 = FDIM*FDIM
#define FILL_BLOCKS  784               // 784*256 = 200704 >= 2n and >= E/4

// ---------------- device scratch (static, no allocation) ----------------
__device__ __align__(128) __half g_xh[N_MAX * FDIM];    // half features (SpMM input)
__device__ __align__(128) __half g_aggh[N_MAX * FDIM];  // half aggregated (GEMM / pool input)
__device__ __align__(128) __half g_Wh[2 * FDIM * FDIM]; // fp16 weights, layers 0/1 only (W2 applied post-pool)
__device__ int   g_deg[2 * N_MAX];
__device__ float g_norm_out[N_MAX];
__device__ float g_norm_in[N_MAX];
__device__ int   g_row_off[N_MAX + 1];
__device__ int   g_cursor[N_MAX];      // initialized to exclusive row offset by k_scan
__device__ int   g_esrc[E_MAX];
__device__ int   g_bsum[64];
__device__ unsigned g_count = 0;            // grid-barrier arrivals
__device__ volatile unsigned g_gen = 0;     // grid-barrier generation (monotonic across replays)

// ---------------- k_prep: fp16 weight conversion (W0, W1) + degree histogram ----------------
__global__ void k_prep(const float* __restrict__ W0, const float* __restrict__ W1,
                       const int* __restrict__ src, const int* __restrict__ dst,
                       int E, int n) {
    if (blockIdx.x < WCONV_BLOCKS) {
        int i = blockIdx.x * 256 + threadIdx.x;   // exactly FDIM*FDIM threads
        g_Wh[i]               = __float2half_rn(__ldg(&W0[i]));
        g_Wh[FDIM * FDIM + i] = __float2half_rn(__ldg(&W1[i]));
    } else {
        const int4* s4 = (const int4*)src;
        const int4* d4 = (const int4*)dst;
        int e4 = E >> 2;
        int nb = gridDim.x - WCONV_BLOCKS;
        int t = (blockIdx.x - WCONV_BLOCKS) * 256 + threadIdx.x;
        for (int i = t; i < e4; i += nb * 256) {
            int4 a = __ldg(&s4[i]);
            int4 b = __ldg(&d4[i]);
            atomicAdd(&g_deg[a.x], 1); atomicAdd(&g_deg[a.y], 1);
            atomicAdd(&g_deg[a.z], 1); atomicAdd(&g_deg[a.w], 1);
            atomicAdd(&g_deg[n + b.x], 1); atomicAdd(&g_deg[n + b.y], 1);
            atomicAdd(&g_deg[n + b.z], 1); atomicAdd(&g_deg[n + b.w], 1);
        }
        int base = e4 << 2;
        if (t < E - base) {
            atomicAdd(&g_deg[src[base + t]], 1);
            atomicAdd(&g_deg[n + dst[base + t]], 1);
        }
    }
}

// ---------------- k_scan: fused two-phase scan with software grid barrier ----------------
__global__ void __launch_bounds__(SCAN_B) k_scan(int n, int nb) {
    __shared__ int wsum[32];
    const int tid = threadIdx.x, lane = tid & 31, wid = tid >> 5;
    const int i = blockIdx.x * SCAN_B + tid;

    int v = 0;
    if (i < n) {
        v = g_deg[n + i];
        g_norm_out[i] = rsqrtf(fmaxf((float)g_deg[i], 1.0f));
        g_norm_in[i]  = rsqrtf(fmaxf((float)v, 1.0f));
    }
    int x = v;
    #pragma unroll
    for (int off = 1; off < 32; off <<= 1) {
        int t = __shfl_up_sync(0xffffffffu, x, off);
        if (lane >= off) x += t;
    }
    if (lane == 31) wsum[wid] = x;
    __syncthreads();
    if (wid == 0) {
        int w = wsum[lane];
        #pragma unroll
        for (int off = 1; off < 32; off <<= 1) {
            int t = __shfl_up_sync(0xffffffffu, w, off);
            if (lane >= off) w += t;
        }
        wsum[lane] = w;
    }
    __syncthreads();
    int incl = x + (wid > 0 ? wsum[wid - 1] : 0);
    if (i < n) g_row_off[i + 1] = incl;
    if (tid == SCAN_B - 1) g_bsum[blockIdx.x] = incl;
    if (i == 0) g_row_off[0] = 0;

    // grid barrier (generation counter; deterministic across replays)
    __syncthreads();
    __threadfence();
    if (tid == 0) {
        unsigned gen = g_gen;
        if (atomicAdd(&g_count, 1u) == gridDim.x - 1) {
            g_count = 0;
            __threadfence();
            g_gen = gen + 1;
        } else {
            while (g_gen == gen) { }
        }
    }
    __syncthreads();
    __threadfence();

    __shared__ int soff;
    if (tid < 32) {
        int l = tid;
        int bid = blockIdx.x;
        int s = (l < nb && l < bid) ? g_bsum[l] : 0;
        if (l + 32 < nb && l + 32 < bid) s += g_bsum[l + 32];
        #pragma unroll
        for (int off = 16; off > 0; off >>= 1)
            s += __shfl_down_sync(0xffffffffu, s, off);
        if (l == 0) soff = s;
    }
    __syncthreads();
    if (i < n) {
        int total = incl + soff;
        g_row_off[i + 1] = total;
        g_cursor[i] = total - v;     // exclusive offset = fill cursor start
    }
}

// ---------------- k_build: CSR fill (single-atomic) + node features, overlapped ----------------
__global__ void k_build(const int* __restrict__ src, const int* __restrict__ dst,
                        int E, int n2,
                        const int* __restrict__ nid, const int* __restrict__ z,
                        const float* __restrict__ init_embed,
                        const float* __restrict__ z_table, int n) {
    if (blockIdx.x < FILL_BLOCKS) {
        int t = blockIdx.x * 256 + threadIdx.x;
        if (t < n2) g_deg[t] = 0;                 // deg is dead; re-zero for next call
        const int4* s4 = (const int4*)src;
        const int4* d4 = (const int4*)dst;
        int e4 = E >> 2;
        for (int i = t; i < e4; i += FILL_BLOCKS * 256) {
            int4 a = __ldg(&s4[i]);
            int4 b = __ldg(&d4[i]);
            g_esrc[atomicAdd(&g_cursor[b.x], 1)] = a.x;
            g_esrc[atomicAdd(&g_cursor[b.y], 1)] = a.y;
            g_esrc[atomicAdd(&g_cursor[b.z], 1)] = a.z;
            g_esrc[atomicAdd(&g_cursor[b.w], 1)] = a.w;
        }
        int base = e4 << 2;
        if (t < E - base) {
            int d = dst[base + t];
            g_esrc[atomicAdd(&g_cursor[d], 1)] = src[base + t];
        }
    } else {
        int total = n * 32;
        int nb = gridDim.x - FILL_BLOCKS;
        for (int idx = (blockIdx.x - FILL_BLOCKS) * 256 + threadIdx.x; idx < total;
             idx += nb * 256) {
            int node = idx >> 5, q = idx & 31;
            float4 v;
            if (q < 16) v = __ldg(&((const float4*)init_embed)[(long)nid[node] * 16 + q]);
            else        v = __ldg(&((const float4*)z_table)[(long)z[node] * 16 + (q - 16)]);
            float s = g_norm_out[node];
            __half2 h0 = __floats2half2_rn(v.x * s, v.y * s);
            __half2 h1 = __floats2half2_rn(v.z * s, v.w * s);
            uint2 pk;
            pk.x = *(unsigned*)&h0;
            pk.y = *(unsigned*)&h1;
            ((uint2*)g_xh)[node * 32 + q] = pk;
        }
    }
}

// ---------------- SpMM gather-reduce: half-warp per dst row (R12 validated form) ----------------
__global__ void __launch_bounds__(256) k_spmm(int n) {
    int row = blockIdx.x * 16 + (threadIdx.x >> 4);
    int hl  = threadIdx.x & 15;
    if (row >= n) return;
    int e0 = g_row_off[row], e1 = g_row_off[row + 1];
    const uint4* xh = (const uint4*)g_xh;   // 16 uint4 per row
    float a0 = 0.f, a1 = 0.f, a2 = 0.f, a3 = 0.f, a4 = 0.f, a5 = 0.f, a6 = 0.f, a7 = 0.f;
    int e = e0;
    for (; e + 3 < e1; e += 4) {
        int s0 = __ldg(&g_esrc[e]);
        int s1 = __ldg(&g_esrc[e + 1]);
        int s2 = __ldg(&g_esrc[e + 2]);
        int s3 = __ldg(&g_esrc[e + 3]);
        uint4 p0 = __ldg(&xh[s0 * 16 + hl]);
        uint4 p1 = __ldg(&xh[s1 * 16 + hl]);
        uint4 p2 = __ldg(&xh[s2 * 16 + hl]);
        uint4 p3 = __ldg(&xh[s3 * 16 + hl]);
        __half2 t0 = __hadd2(__hadd2(*(__half2*)&p0.x, *(__half2*)&p1.x),
                             __hadd2(*(__half2*)&p2.x, *(__half2*)&p3.x));
        __half2 t1 = __hadd2(__hadd2(*(__half2*)&p0.y, *(__half2*)&p1.y),
                             __hadd2(*(__half2*)&p2.y, *(__half2*)&p3.y));
        __half2 t2 = __hadd2(__hadd2(*(__half2*)&p0.z, *(__half2*)&p1.z),
                             __hadd2(*(__half2*)&p2.z, *(__half2*)&p3.z));
        __half2 t3 = __hadd2(__hadd2(*(__half2*)&p0.w, *(__half2*)&p1.w),
                             __hadd2(*(__half2*)&p2.w, *(__half2*)&p3.w));
        float2 f;
        f = __half22float2(t0); a0 += f.x; a1 += f.y;
        f = __half22float2(t1); a2 += f.x; a3 += f.y;
        f = __half22float2(t2); a4 += f.x; a5 += f.y;
        f = __half22float2(t3); a6 += f.x; a7 += f.y;
    }
    for (; e < e1; e++) {
        int s0 = __ldg(&g_esrc[e]);
        uint4 p0 = __ldg(&xh[s0 * 16 + hl]);
        float2 f;
        f = __half22float2(*(__half2*)&p0.x); a0 += f.x; a1 += f.y;
        f = __half22float2(*(__half2*)&p0.y); a2 += f.x; a3 += f.y;
        f = __half22float2(*(__half2*)&p0.z); a4 += f.x; a5 += f.y;
        f = __half22float2(*(__half2*)&p0.w); a6 += f.x; a7 += f.y;
    }
    float ni = g_norm_in[row];
    __half2 h0 = __floats2half2_rn(a0 * ni, a1 * ni);
    __half2 h1 = __floats2half2_rn(a2 * ni, a3 * ni);
    __half2 h2 = __floats2half2_rn(a4 * ni, a5 * ni);
    __half2 h3 = __floats2half2_rn(a6 * ni, a7 * ni);
    uint4 pk;
    pk.x = *(unsigned*)&h0;
    pk.y = *(unsigned*)&h1;
    pk.z = *(unsigned*)&h2;
    pk.w = *(unsigned*)&h3;
    ((uint4*)g_aggh)[row * 16 + hl] = pk;
}

// ---------------- HMMA GEMM (layers 0/1 only): g_xh = relu(g_aggh @ g_Wh[layer] + b) * norm_out ----------------
__global__ void __launch_bounds__(256, 3) k_gemm_h(int layer,
                                                   const float* __restrict__ bias,
                                                   int n) {
    extern __shared__ __half sh[];
    __half* As = sh;               // [128][AP]
    __half* Ws = sh + 128 * AP;    // [128][AP]
    const int tid = threadIdx.x;
    const int w = tid >> 5, lane = tid & 31;
    const int row0 = blockIdx.x * 128;

    {
        const uint4* asrc = (const uint4*)g_aggh;
        const uint4* wsrc = (const uint4*)(g_Wh + layer * FDIM * FDIM);
        int r = tid >> 1;
        int s0 = (tid & 1) * 8;
        int grow = row0 + r;
        #pragma unroll
        for (int s = 0; s < 8; s++) {
            uint4 av = make_uint4(0u, 0u, 0u, 0u);
            if (grow < n) av = __ldg(&asrc[grow * 16 + s0 + s]);
            *(uint4*)&As[r * AP + (s0 + s) * 8] = av;
            uint4 wv = __ldg(&wsrc[r * 16 + s0 + s]);
            *(uint4*)&Ws[r * AP + (s0 + s) * 8] = wv;
        }
    }
    __syncthreads();

    float acc[16][4];
    #pragma unroll
    for (int nt = 0; nt < 16; nt++)
        #pragma unroll
        for (int q = 0; q < 4; q++) acc[nt][q] = 0.f;

    #pragma unroll
    for (int kk = 0; kk < 8; kk++) {
        unsigned a0, a1, a2, a3;
        {
            int arow = 16 * w + (lane & 15);
            int acol = kk * 16 + ((lane >> 4) << 3);
            unsigned aaddr = (unsigned)__cvta_generic_to_shared(&As[arow * AP + acol]);
            asm volatile("ldmatrix.sync.aligned.m8n8.x4.shared.b16 {%0,%1,%2,%3}, [%4];"
                         : "=r"(a0), "=r"(a1), "=r"(a2), "=r"(a3) : "r"(aaddr));
        }
        int brow = kk * 16 + (lane & 15);
        unsigned bbase = (unsigned)__cvta_generic_to_shared(&Ws[brow * AP]);
        #pragma unroll
        for (int nt = 0; nt < 16; nt++) {
            unsigned b0, b1;
            asm volatile("ldmatrix.sync.aligned.m8n8.x2.trans.shared.b16 {%0,%1}, [%2];"
                         : "=r"(b0), "=r"(b1) : "r"(bbase + nt * 16u));
            asm volatile("mma.sync.aligned.m16n8k16.row.col.f32.f16.f16.f32 "
                         "{%0,%1,%2,%3}, {%4,%5,%6,%7}, {%8,%9}, {%0,%1,%2,%3};"
                         : "+f"(acc[nt][0]), "+f"(acc[nt][1]), "+f"(acc[nt][2]), "+f"(acc[nt][3])
                         : "r"(a0), "r"(a1), "r"(a2), "r"(a3), "r"(b0), "r"(b1));
        }
    }

    const int rlo = row0 + 16 * w + (lane >> 2);
    const int rhi = rlo + 8;
    const int cbase = (lane & 3) * 2;
    float slo = 1.f, shi = 1.f;
    if (rlo < n) slo = g_norm_out[rlo];
    if (rhi < n) shi = g_norm_out[rhi];
    #pragma unroll
    for (int nt = 0; nt < 16; nt++) {
        int c = nt * 8 + cbase;
        float b0v = __ldg(&bias[c]), b1v = __ldg(&bias[c + 1]);
        if (rlo < n) {
            __half2 h = __floats2half2_rn(fmaxf(acc[nt][0] + b0v, 0.f) * slo,
                                          fmaxf(acc[nt][1] + b1v, 0.f) * slo);
            *(__half2*)&g_xh[rlo * FDIM + c] = h;
        }
        if (rhi < n) {
            __half2 h = __floats2half2_rn(fmaxf(acc[nt][2] + b0v, 0.f) * shi,
                                          fmaxf(acc[nt][3] + b1v, 0.f) * shi);
            *(__half2*)&g_xh[rhi * FDIM + c] = h;
        }
    }
}

// ---------------- fused pooling + W2/b2 + MLP head ----------------
// Linearity: segment_sum(agg2 @ W2 + b2) = segment_sum(agg2) @ W2 + cnt * b2.
// Pools g_aggh directly (layer-2 GEMM over nodes eliminated).
__global__ void __launch_bounds__(256) k_pool_mlp(const int* __restrict__ gid, int n,
                                                  const float* __restrict__ W2,
                                                  const float* __restrict__ b2,
                                                  const float* __restrict__ lin1_W,
                                                  const float* __restrict__ lin1_b,
                                                  const float* __restrict__ lin2_W,
                                                  const float* __restrict__ lin2_b,
                                                  float* __restrict__ out) {
    __shared__ float gp[4][FDIM];   // per-group partial sums
    __shared__ float pa[FDIM];      // pooled agg
    __shared__ float gs[FDIM];      // pooled agg @ W2 + cnt*b2
    __shared__ float hs[FDIM];
    __shared__ int s_lo, s_hi;
    const int g = blockIdx.x;
    const int tid = threadIdx.x;
    const int grp = tid >> 6;       // node group 0..3
    const int col = tid & 63;       // half2 column 0..63

    if (tid == 0) {
        int lo = 0, hi = n;
        while (lo < hi) { int m = (lo + hi) >> 1; if (__ldg(&gid[m]) < g) lo = m + 1; else hi = m; }
        s_lo = lo;
    } else if (tid == 32) {
        int lo = 0, hi = n;
        while (lo < hi) { int m = (lo + hi) >> 1; if (__ldg(&gid[m]) <= g) lo = m + 1; else hi = m; }
        s_hi = lo;
    }
    __syncthreads();

    const int lo = s_lo, hi = s_hi;
    {
        float acc0 = 0.f, acc1 = 0.f;
        const __half2* ah2 = (const __half2*)g_aggh;
        for (int node = lo + grp; node < hi; node += 4) {
            float2 f = __half22float2(ah2[node * 64 + col]);
            acc0 += f.x; acc1 += f.y;
        }
        gp[grp][2 * col]     = acc0;
        gp[grp][2 * col + 1] = acc1;
    }
    __syncthreads();
    if (tid < FDIM)
        pa[tid] = gp[0][tid] + gp[1][tid] + gp[2][tid] + gp[3][tid];
    __syncthreads();
    // gs = pa @ W2 + cnt * b2
    if (tid < FDIM) {
        float acc = (float)(hi - lo) * __ldg(&b2[tid]);
        #pragma unroll 8
        for (int k = 0; k < FDIM; k++)
            acc += pa[k] * __ldg(&W2[k * FDIM + tid]);
        gs[tid] = acc;
    }
    __syncthreads();
    if (tid < FDIM) {
        float acc = __ldg(&lin1_b[tid]);
        #pragma unroll 8
        for (int k = 0; k < FDIM; k++)
            acc += gs[k] * __ldg(&lin1_W[k * FDIM + tid]);
        hs[tid] = fmaxf(acc, 0.f);
    }
    __syncthreads();
    for (int c = tid; c < OUTD; c += blockDim.x) {
        float acc = __ldg(&lin2_b[c]);
        #pragma unroll 8
        for (int k = 0; k < FDIM; k++)
            acc += hs[k] * __ldg(&lin2_W[k * OUTD + c]);
        out[g * OUTD + c] = acc;
    }
}

// ---------------- launch ----------------
extern "C" void kernel_launch(void* const* d_in, const int* in_sizes, int n_in,
                              void* d_out, int out_size) {
    const int*   nid        = (const int*)  d_in[0];
    const int*   z          = (const int*)  d_in[1];
    const int*   src        = (const int*)  d_in[2];
    const int*   dst        = (const int*)  d_in[3];
    const int*   graph_id   = (const int*)  d_in[4];
    const float* init_embed = (const float*)d_in[5];
    const float* z_table    = (const float*)d_in[6];
    const float* W0 = (const float*)d_in[7];
    const float* b0 = (const float*)d_in[8];
    const float* W1 = (const float*)d_in[9];
    const float* b1 = (const float*)d_in[10];
    const float* W2 = (const float*)d_in[11];
    const float* b2 = (const float*)d_in[12];
    const float* lin1_W = (const float*)d_in[13];
    const float* lin1_b = (const float*)d_in[14];
    const float* lin2_W = (const float*)d_in[15];
    const float* lin2_b = (const float*)d_in[16];
    float* out = (float*)d_out;

    const int n = in_sizes[0];       // 50000
    const int E = in_sizes[2];       // 800000
    const int nb = (n + SCAN_B - 1) / SCAN_B;   // 49

    cudaFuncSetAttribute(k_gemm_h, cudaFuncAttributeMaxDynamicSharedMemorySize, GEMM_SMEM);

    // 1) weights fp16 (W0, W1) + degree histogram (one kernel, disjoint block ranges)
    int deg_blocks = ((E >> 2) + 255) / 256;
    k_prep<<<WCONV_BLOCKS + deg_blocks, 256>>>(W0, W1, src, dst, E, n);

    // 2) fused scan (norms + CSR row offsets + fill cursors) with in-kernel grid barrier
    k_scan<<<nb, SCAN_B>>>(n, nb);

    // 3) CSR fill + node features (one kernel, disjoint block ranges)
    int feat_blocks = (n * 32 + 255) / 256;
    k_build<<<FILL_BLOCKS + feat_blocks, 256>>>(src, dst, E, 2 * n,
                                                nid, z, init_embed, z_table, n);

    // 4) GCN layers: two full (spmm+gemm) layers, then spmm only (W2 folded into head)
    const int spmm_blocks = (n + 15) / 16;
    const int gemm_blocks = (n + 127) / 128;
    k_spmm<<<spmm_blocks, 256>>>(n);
    k_gemm_h<<<gemm_blocks, 256, GEMM_SMEM>>>(0, b0, n);
    k_spmm<<<spmm_blocks, 256>>>(n);
    k_gemm_h<<<gemm_blocks, 256, GEMM_SMEM>>>(1, b1, n);
    k_spmm<<<spmm_blocks, 256>>>(n);

    // 5) fused pooling + W2/b2 + MLP head
    k_pool_mlp<<<G_CNT, 256>>>(graph_id, n, W2, b2,
                               lin1_W, lin1_b, lin2_W, lin2_b, out);
}